// round 8
// baseline (speedup 1.0000x reference)
#include <cuda_runtime.h>
#include <cuda_fp16.h>
#include <cstdint>

#define D          256
#define NCODES     1024
#define ROWS_TOTAL 16384
#define BM         128
#define BN         256
#define NKCH       4         // K=256, chunks of 64
#define NITER      4         // NCODES / BN
#define CAP        16        // candidate list capacity per row

#define ASTRIDE_B   160
#define A_STAGE     (BM * ASTRIDE_B)              // 20480
#define B_STAGE     (BN * ASTRIDE_B)              // 40960
#define STAGE_BYTES (A_STAGE + B_STAGE)           // 61440
#define B_OFF       A_STAGE
#define EHALF_OFF   (2 * STAGE_BYTES)             // 122880
#define XSQ_OFF     (EHALF_OFF + NCODES * 4)      // 126976
#define SMAX_OFF    (XSQ_OFF + BM * 4)            // 127488
#define SCNT_OFF    (SMAX_OFF + BM * 4)           // 128000
#define SIDX_OFF    (SCNT_OFF + BM * 4)           // 128512
#define SLIST_OFF   (SIDX_OFF + BM * 4)           // 129024
#define SMEM_TOTAL  (SLIST_OFF + BM * CAP * 4)    // 137216

__device__ __half g_Xc[(size_t)ROWS_TOTAL * D];    // 8 MB  (fp16 hi, mma-interleaved)
__device__ __half g_Ec[(size_t)NCODES * D];        // 0.5 MB
__device__ float  g_e_half[NCODES];
__device__ float  g_xsq[ROWS_TOTAL];
__device__ int    g_maxEsq_bits;

__device__ __forceinline__ constexpr int ilv16(int k) {   // fragment interleave in 16-group
    return 4 * ((k & 7) >> 1) + 2 * (k >> 3) + (k & 1);
}
// orderable-uint encoding of float (monotone for atomicMax)
__device__ __forceinline__ unsigned fenc(float f) {
    unsigned u = __float_as_uint(f);
    return (u & 0x80000000u) ? ~u : (u | 0x80000000u);
}
__device__ __forceinline__ float fdec(unsigned u) {
    return __uint_as_float((u & 0x80000000u) ? (u ^ 0x80000000u) : ~u);
}

__global__ void init_kernel() { g_maxEsq_bits = 0; }

// one thread per 16-elem group: convert+interleave; fold row-sum-of-squares reduction
__global__ void prep_x(const float* __restrict__ X) {
    int gi = blockIdx.x * blockDim.x + threadIdx.x;       // ROWS_TOTAL*16 groups
    const float4* src = reinterpret_cast<const float4*>(X) + (size_t)gi * 4;
    float4 v0 = src[0], v1 = src[1], v2 = src[2], v3 = src[3];
    float f[16] = { v0.x, v0.y, v0.z, v0.w, v1.x, v1.y, v1.z, v1.w,
                    v2.x, v2.y, v2.z, v2.w, v3.x, v3.y, v3.z, v3.w };
    __half h[16];
    float s = 0.f;
#pragma unroll
    for (int j = 0; j < 16; j++) { h[ilv16(j)] = __float2half_rn(f[j]); s += f[j] * f[j]; }
    uint4* dst = reinterpret_cast<uint4*>(g_Xc) + (size_t)gi * 2;
    dst[0] = reinterpret_cast<const uint4*>(h)[0];
    dst[1] = reinterpret_cast<const uint4*>(h)[1];
#pragma unroll
    for (int off = 8; off > 0; off >>= 1)
        s += __shfl_down_sync(0xffffffffu, s, off, 16);
    if ((gi & 15) == 0) g_xsq[gi >> 4] = s;
}

__global__ void prep_e(const float* __restrict__ E) {
    int gi = blockIdx.x * blockDim.x + threadIdx.x;       // NCODES*16 groups
    const float4* src = reinterpret_cast<const float4*>(E) + (size_t)gi * 4;
    float4 v0 = src[0], v1 = src[1], v2 = src[2], v3 = src[3];
    float f[16] = { v0.x, v0.y, v0.z, v0.w, v1.x, v1.y, v1.z, v1.w,
                    v2.x, v2.y, v2.z, v2.w, v3.x, v3.y, v3.z, v3.w };
    __half h[16];
    float s = 0.f;
#pragma unroll
    for (int j = 0; j < 16; j++) { h[ilv16(j)] = __float2half_rn(f[j]); s += f[j] * f[j]; }
    uint4* dst = reinterpret_cast<uint4*>(g_Ec) + (size_t)gi * 2;
    dst[0] = reinterpret_cast<const uint4*>(h)[0];
    dst[1] = reinterpret_cast<const uint4*>(h)[1];
#pragma unroll
    for (int off = 8; off > 0; off >>= 1)
        s += __shfl_down_sync(0xffffffffu, s, off, 16);
    if ((gi & 15) == 0) {
        g_e_half[gi >> 4] = 0.5f * s;
        atomicMax(&g_maxEsq_bits, __float_as_int(s));     // s >= 0: int-bits monotone
    }
}

static __device__ __forceinline__ uint32_t smem_u32(const void* p) {
    uint32_t a;
    asm("{ .reg .u64 t; cvta.to.shared.u64 t, %1; cvt.u32.u64 %0, t; }" : "=r"(a) : "l"(p));
    return a;
}
#define CP16(dst, src) asm volatile("cp.async.cg.shared.global [%0], [%1], 16;" :: "r"(dst), "l"(src) : "memory")
#define LDS64(r0, r1, a) asm volatile("ld.shared.v2.b32 {%0,%1}, [%2];" : "=r"(r0), "=r"(r1) : "r"(a))
#define MMA_F16(c, a, b) \
    asm volatile("mma.sync.aligned.m16n8k16.row.col.f32.f16.f16.f32 " \
                 "{%0,%1,%2,%3}, {%4,%5,%6,%7}, {%8,%9}, {%0,%1,%2,%3};" \
                 : "+f"((c)[0]), "+f"((c)[1]), "+f"((c)[2]), "+f"((c)[3]) \
                 : "r"((a)[0]), "r"((a)[1]), "r"((a)[2]), "r"((a)[3]), "r"((b)[0]), "r"((b)[1]))

__global__ __launch_bounds__(256, 1)
void vq_mma(const float* __restrict__ X, const float* __restrict__ E,
            float* __restrict__ out) {
    extern __shared__ char smem[];
    const uint32_t sb = smem_u32(smem);
    float*    ehs   = (float*)(smem + EHALF_OFF);
    float*    sXsq  = (float*)(smem + XSQ_OFF);
    unsigned* sMax  = (unsigned*)(smem + SMAX_OFF);
    int*      sCnt  = (int*)(smem + SCNT_OFF);
    int*      sIdx  = (int*)(smem + SIDX_OFF);
    int*      sList = (int*)(smem + SLIST_OFF);

    const int tid  = threadIdx.x;
    const int lane = tid & 31, wid = tid >> 5;
    const int wm = wid & 1, wn = wid >> 1;
    const int g = lane >> 2, t = lane & 3;
    const int row0 = blockIdx.x * BM;
    const float maxEsq = __int_as_float(g_maxEsq_bits);

    for (int i = tid; i < NCODES; i += 256) ehs[i] = g_e_half[i];
    if (tid < BM) {
        sXsq[tid] = g_xsq[row0 + tid];
        sMax[tid] = 0u;            // below enc(-inf)
        sCnt[tid] = 0;
    }

    const int urow = tid >> 3, uj = tid & 7;
    const char* aSrc0 = (const char*)(g_Xc + (size_t)(row0 + urow) * D) + uj * 16;
    const uint32_t aDst0 = sb + urow * ASTRIDE_B + uj * 16;
    const uint32_t bDst0 = sb + B_OFF + urow * ASTRIDE_B + uj * 16;
    const uint32_t aLds0 = sb + (uint32_t)((wm * 64 + g) * ASTRIDE_B + t * 8);
    const uint32_t bLds0 = sb + (uint32_t)(B_OFF + (wn * 64 + g) * ASTRIDE_B + t * 8);
    __syncthreads();

    for (int ni = 0; ni < NITER; ni++) {
        const int n0 = ni * BN;
        const char* bSrc0 = (const char*)(g_Ec + (size_t)(n0 + urow) * D) + uj * 16;

        float acc[4][8][4];
#pragma unroll
        for (int mi = 0; mi < 4; mi++)
#pragma unroll
            for (int nj = 0; nj < 8; nj++)
#pragma unroll
                for (int q = 0; q < 4; q++) acc[mi][nj][q] = 0.f;

        {   // prologue: chunk 0 -> stage 0
#pragma unroll
            for (int i = 0; i < 4; i++) CP16(aDst0 + i * (32 * ASTRIDE_B), aSrc0 + i * 16384);
#pragma unroll
            for (int i = 0; i < 8; i++) CP16(bDst0 + i * (32 * ASTRIDE_B), bSrc0 + i * 16384);
            asm volatile("cp.async.commit_group;" ::: "memory");
        }

        for (int kc = 0; kc < NKCH; kc++) {
            const uint32_t st = (uint32_t)(kc & 1) * STAGE_BYTES;

            if (kc + 1 < NKCH) {
                const int kn = kc + 1;
                const uint32_t nst = (uint32_t)(kn & 1) * STAGE_BYTES;
#pragma unroll
                for (int i = 0; i < 4; i++)
                    CP16(nst + aDst0 + i * (32 * ASTRIDE_B), aSrc0 + kn * 128 + i * 16384);
#pragma unroll
                for (int i = 0; i < 8; i++)
                    CP16(nst + bDst0 + i * (32 * ASTRIDE_B), bSrc0 + kn * 128 + i * 16384);
                asm volatile("cp.async.commit_group;" ::: "memory");
                asm volatile("cp.async.wait_group 1;" ::: "memory");
            } else {
                asm volatile("cp.async.wait_group 0;" ::: "memory");
            }
            __syncthreads();

#pragma unroll
            for (int s = 0; s < 4; s++) {
                uint32_t a[4][4];
#pragma unroll
                for (int mi = 0; mi < 4; mi++) {
                    uint32_t ad = st + aLds0 + (uint32_t)(mi * 16 * ASTRIDE_B + s * 32);
                    LDS64(a[mi][0], a[mi][2], ad);
                    LDS64(a[mi][1], a[mi][3], ad + 8 * ASTRIDE_B);
                }
                uint32_t b[8][2];
#pragma unroll
                for (int nj = 0; nj < 8; nj++) {
                    uint32_t bd = st + bLds0 + (uint32_t)(nj * 8 * ASTRIDE_B + s * 32);
                    LDS64(b[nj][0], b[nj][1], bd);
                }
#pragma unroll
                for (int mi = 0; mi < 4; mi++)
#pragma unroll
                    for (int nj = 0; nj < 8; nj++)
                        MMA_F16(acc[mi][nj], a[mi], b[nj]);
            }
            __syncthreads();
        }

        // ---- Phase A: subtract e_half in place, per-row running max ----
#pragma unroll
        for (int mi = 0; mi < 4; mi++)
#pragma unroll
            for (int qh = 0; qh < 2; qh++) {
                const int r = wm * 64 + mi * 16 + g + 8 * qh;
                float m = -3.4e38f;
#pragma unroll
                for (int nj = 0; nj < 8; nj++) {
                    const int n = n0 + wn * 64 + nj * 8 + 2 * t;
                    acc[mi][nj][2 * qh]     -= ehs[n];
                    acc[mi][nj][2 * qh + 1] -= ehs[n + 1];
                    m = fmaxf(m, fmaxf(acc[mi][nj][2 * qh], acc[mi][nj][2 * qh + 1]));
                }
                atomicMax(&sMax[r], fenc(m));
            }
        __syncthreads();

        // ---- Phase B: collect candidates within certified margin of running max ----
#pragma unroll
        for (int mi = 0; mi < 4; mi++)
#pragma unroll
            for (int qh = 0; qh < 2; qh++) {
                const int r = wm * 64 + mi * 16 + g + 8 * qh;
                const float thr = fdec(sMax[r])
                                - (0.002f * sqrtf(sXsq[r] * maxEsq) + 0.03f);
#pragma unroll
                for (int nj = 0; nj < 8; nj++) {
                    const int n = n0 + wn * 64 + nj * 8 + 2 * t;
                    if (acc[mi][nj][2 * qh] >= thr) {
                        int p = atomicAdd(&sCnt[r], 1);
                        if (p < CAP) sList[r * CAP + p] = n;
                    }
                    if (acc[mi][nj][2 * qh + 1] >= thr) {
                        int p = atomicAdd(&sCnt[r], 1);
                        if (p < CAP) sList[r * CAP + p] = n + 1;
                    }
                }
            }
        __syncthreads();
    }

    // ---- exact fp64 rescore of candidates: one warp per 16 rows ----
    for (int r = wid * 16; r < wid * 16 + 16; r++) {
        const float4* X4 = reinterpret_cast<const float4*>(X + (size_t)(row0 + r) * D);
        float4 x0 = X4[2 * lane], x1 = X4[2 * lane + 1];   // 8 floats per lane
        int cnt = sCnt[r];
        double bestv = -1e300;
        int    besti = NCODES;
        const bool fallback = (cnt > CAP);
        const int  total = fallback ? NCODES : cnt;
        for (int c = 0; c < total; c++) {
            const int idx = fallback ? c : sList[r * CAP + c];
            const float4* E4r = reinterpret_cast<const float4*>(E + (size_t)idx * D);
            float4 e0 = E4r[2 * lane], e1 = E4r[2 * lane + 1];
            double sc =
                  (double)x0.x * e0.x + (double)x0.y * e0.y
                + (double)x0.z * e0.z + (double)x0.w * e0.w
                + (double)x1.x * e1.x + (double)x1.y * e1.y
                + (double)x1.z * e1.z + (double)x1.w * e1.w
                - 0.5 * ((double)e0.x * e0.x + (double)e0.y * e0.y
                       + (double)e0.z * e0.z + (double)e0.w * e0.w
                       + (double)e1.x * e1.x + (double)e1.y * e1.y
                       + (double)e1.z * e1.z + (double)e1.w * e1.w);
#pragma unroll
            for (int off = 16; off > 0; off >>= 1)
                sc += __shfl_xor_sync(0xffffffffu, sc, off);
            if (sc > bestv || (sc == bestv && idx < besti)) { bestv = sc; besti = idx; }
        }
        if (lane == 0) sIdx[r] = besti;
    }
    __syncthreads();

    // ---- gather: out[row] = E[best] (coalesced float4) ----
    const float4* E4 = reinterpret_cast<const float4*>(E);
    float4*       O4 = reinterpret_cast<float4*>(out);
    const int col = tid & 63;
#pragma unroll
    for (int r = tid >> 6; r < BM; r += 4) {
        int idx = sIdx[r];
        O4[(size_t)(row0 + r) * (D / 4) + col] = E4[(size_t)idx * (D / 4) + col];
    }
}

extern "C" void kernel_launch(void* const* d_in, const int* in_sizes, int n_in,
                              void* d_out, int out_size) {
    const float* x = (const float*)d_in[0];     // [16,1024,256] f32
    const float* E = (const float*)d_in[1];     // [1024,256]    f32
    float* out = (float*)d_out;

    init_kernel<<<1, 1>>>();
    prep_e<<<NCODES * 16 / 256, 256>>>(E);
    prep_x<<<ROWS_TOTAL * 16 / 256, 256>>>(x);

    cudaFuncSetAttribute(vq_mma, cudaFuncAttributeMaxDynamicSharedMemorySize, SMEM_TOTAL);
    vq_mma<<<ROWS_TOTAL / BM, 256, SMEM_TOTAL>>>(x, E, out);
}

// round 9
// speedup vs baseline: 1.1134x; 1.1134x over previous
#include <cuda_runtime.h>
#include <cuda_fp16.h>
#include <cstdint>

#define D          256
#define NCODES     1024
#define ROWS_TOTAL 16384
#define BM         128
#define BN         256
#define NKCH       4         // K=256, chunks of 64
#define NITER      4         // NCODES / BN
#define CAP        16        // candidate list capacity per row

#define ASTRIDE_B   160
#define A_STAGE     (BM * ASTRIDE_B)              // 20480
#define B_STAGE     (BN * ASTRIDE_B)              // 40960
#define STAGE_BYTES (A_STAGE + B_STAGE)           // 61440
#define B_OFF       A_STAGE
#define EHALF_OFF   (2 * STAGE_BYTES)             // 122880
#define XSQ_OFF     (EHALF_OFF + NCODES * 4)      // 126976
#define SMAX_OFF    (XSQ_OFF + BM * 4)            // 127488
#define SCNT_OFF    (SMAX_OFF + BM * 4)           // 128000
#define SLIST_OFF   (SCNT_OFF + BM * 4)           // 128512
#define SMEM_TOTAL  (SLIST_OFF + BM * CAP * 4)    // 136704

__device__ __half g_Xc[(size_t)ROWS_TOTAL * D];    // 8 MB  (fp16 hi, mma-interleaved)
__device__ __half g_Ec[(size_t)NCODES * D];        // 0.5 MB
__device__ float  g_e_half[NCODES];
__device__ float  g_xsq[ROWS_TOTAL];
__device__ int    g_maxEsq_bits;
__device__ int    g_cnt[ROWS_TOTAL];               // candidate counts
__device__ int    g_list[ROWS_TOTAL * CAP];        // candidate indices (1 MB)

__device__ __forceinline__ constexpr int ilv16(int k) {   // fragment interleave in 16-group
    return 4 * ((k & 7) >> 1) + 2 * (k >> 3) + (k & 1);
}
__device__ __forceinline__ unsigned fenc(float f) {       // orderable-uint float encoding
    unsigned u = __float_as_uint(f);
    return (u & 0x80000000u) ? ~u : (u | 0x80000000u);
}
__device__ __forceinline__ float fdec(unsigned u) {
    return __uint_as_float((u & 0x80000000u) ? (u ^ 0x80000000u) : ~u);
}

__global__ void init_kernel() { g_maxEsq_bits = 0; }

__global__ void prep_x(const float* __restrict__ X) {
    int gi = blockIdx.x * blockDim.x + threadIdx.x;       // ROWS_TOTAL*16 groups
    const float4* src = reinterpret_cast<const float4*>(X) + (size_t)gi * 4;
    float4 v0 = src[0], v1 = src[1], v2 = src[2], v3 = src[3];
    float f[16] = { v0.x, v0.y, v0.z, v0.w, v1.x, v1.y, v1.z, v1.w,
                    v2.x, v2.y, v2.z, v2.w, v3.x, v3.y, v3.z, v3.w };
    __half h[16];
    float s = 0.f;
#pragma unroll
    for (int j = 0; j < 16; j++) { h[ilv16(j)] = __float2half_rn(f[j]); s += f[j] * f[j]; }
    uint4* dst = reinterpret_cast<uint4*>(g_Xc) + (size_t)gi * 2;
    dst[0] = reinterpret_cast<const uint4*>(h)[0];
    dst[1] = reinterpret_cast<const uint4*>(h)[1];
#pragma unroll
    for (int off = 8; off > 0; off >>= 1)
        s += __shfl_down_sync(0xffffffffu, s, off, 16);
    if ((gi & 15) == 0) g_xsq[gi >> 4] = s;
}

__global__ void prep_e(const float* __restrict__ E) {
    int gi = blockIdx.x * blockDim.x + threadIdx.x;       // NCODES*16 groups
    const float4* src = reinterpret_cast<const float4*>(E) + (size_t)gi * 4;
    float4 v0 = src[0], v1 = src[1], v2 = src[2], v3 = src[3];
    float f[16] = { v0.x, v0.y, v0.z, v0.w, v1.x, v1.y, v1.z, v1.w,
                    v2.x, v2.y, v2.z, v2.w, v3.x, v3.y, v3.z, v3.w };
    __half h[16];
    float s = 0.f;
#pragma unroll
    for (int j = 0; j < 16; j++) { h[ilv16(j)] = __float2half_rn(f[j]); s += f[j] * f[j]; }
    uint4* dst = reinterpret_cast<uint4*>(g_Ec) + (size_t)gi * 2;
    dst[0] = reinterpret_cast<const uint4*>(h)[0];
    dst[1] = reinterpret_cast<const uint4*>(h)[1];
#pragma unroll
    for (int off = 8; off > 0; off >>= 1)
        s += __shfl_down_sync(0xffffffffu, s, off, 16);
    if ((gi & 15) == 0) {
        g_e_half[gi >> 4] = 0.5f * s;
        atomicMax(&g_maxEsq_bits, __float_as_int(s));
    }
}

static __device__ __forceinline__ uint32_t smem_u32(const void* p) {
    uint32_t a;
    asm("{ .reg .u64 t; cvta.to.shared.u64 t, %1; cvt.u32.u64 %0, t; }" : "=r"(a) : "l"(p));
    return a;
}
#define CP16(dst, src) asm volatile("cp.async.cg.shared.global [%0], [%1], 16;" :: "r"(dst), "l"(src) : "memory")
#define LDS64(r0, r1, a) asm volatile("ld.shared.v2.b32 {%0,%1}, [%2];" : "=r"(r0), "=r"(r1) : "r"(a))
#define MMA_F16(c, a, b) \
    asm volatile("mma.sync.aligned.m16n8k16.row.col.f32.f16.f16.f32 " \
                 "{%0,%1,%2,%3}, {%4,%5,%6,%7}, {%8,%9}, {%0,%1,%2,%3};" \
                 : "+f"((c)[0]), "+f"((c)[1]), "+f"((c)[2]), "+f"((c)[3]) \
                 : "r"((a)[0]), "r"((a)[1]), "r"((a)[2]), "r"((a)[3]), "r"((b)[0]), "r"((b)[1]))

__global__ __launch_bounds__(256, 1)
void vq_mma() {
    extern __shared__ char smem[];
    const uint32_t sb = smem_u32(smem);
    float*    ehs   = (float*)(smem + EHALF_OFF);
    float*    sXsq  = (float*)(smem + XSQ_OFF);
    unsigned* sMax  = (unsigned*)(smem + SMAX_OFF);
    int*      sCnt  = (int*)(smem + SCNT_OFF);
    int*      sList = (int*)(smem + SLIST_OFF);

    const int tid  = threadIdx.x;
    const int lane = tid & 31, wid = tid >> 5;
    const int wm = wid & 1, wn = wid >> 1;
    const int g = lane >> 2, t = lane & 3;
    const int row0 = blockIdx.x * BM;
    const float maxEsq = __int_as_float(g_maxEsq_bits);

    for (int i = tid; i < NCODES; i += 256) ehs[i] = g_e_half[i];
    if (tid < BM) {
        sXsq[tid] = g_xsq[row0 + tid];
        sMax[tid] = 0u;
        sCnt[tid] = 0;
    }

    const int urow = tid >> 3, uj = tid & 7;
    const char* aSrc0 = (const char*)(g_Xc + (size_t)(row0 + urow) * D) + uj * 16;
    const uint32_t aDst0 = sb + urow * ASTRIDE_B + uj * 16;
    const uint32_t bDst0 = sb + B_OFF + urow * ASTRIDE_B + uj * 16;
    const uint32_t aLds0 = sb + (uint32_t)((wm * 64 + g) * ASTRIDE_B + t * 8);
    const uint32_t bLds0 = sb + (uint32_t)(B_OFF + (wn * 64 + g) * ASTRIDE_B + t * 8);
    __syncthreads();

    for (int ni = 0; ni < NITER; ni++) {
        const int n0 = ni * BN;
        const char* bSrc0 = (const char*)(g_Ec + (size_t)(n0 + urow) * D) + uj * 16;

        float acc[4][8][4];
#pragma unroll
        for (int mi = 0; mi < 4; mi++)
#pragma unroll
            for (int nj = 0; nj < 8; nj++)
#pragma unroll
                for (int q = 0; q < 4; q++) acc[mi][nj][q] = 0.f;

        {   // prologue: chunk 0 -> stage 0
#pragma unroll
            for (int i = 0; i < 4; i++) CP16(aDst0 + i * (32 * ASTRIDE_B), aSrc0 + i * 16384);
#pragma unroll
            for (int i = 0; i < 8; i++) CP16(bDst0 + i * (32 * ASTRIDE_B), bSrc0 + i * 16384);
            asm volatile("cp.async.commit_group;" ::: "memory");
        }

        for (int kc = 0; kc < NKCH; kc++) {
            const uint32_t st = (uint32_t)(kc & 1) * STAGE_BYTES;

            if (kc + 1 < NKCH) {
                const int kn = kc + 1;
                const uint32_t nst = (uint32_t)(kn & 1) * STAGE_BYTES;
#pragma unroll
                for (int i = 0; i < 4; i++)
                    CP16(nst + aDst0 + i * (32 * ASTRIDE_B), aSrc0 + kn * 128 + i * 16384);
#pragma unroll
                for (int i = 0; i < 8; i++)
                    CP16(nst + bDst0 + i * (32 * ASTRIDE_B), bSrc0 + kn * 128 + i * 16384);
                asm volatile("cp.async.commit_group;" ::: "memory");
                asm volatile("cp.async.wait_group 1;" ::: "memory");
            } else {
                asm volatile("cp.async.wait_group 0;" ::: "memory");
            }
            __syncthreads();

#pragma unroll
            for (int s = 0; s < 4; s++) {
                uint32_t a[4][4];
#pragma unroll
                for (int mi = 0; mi < 4; mi++) {
                    uint32_t ad = st + aLds0 + (uint32_t)(mi * 16 * ASTRIDE_B + s * 32);
                    LDS64(a[mi][0], a[mi][2], ad);
                    LDS64(a[mi][1], a[mi][3], ad + 8 * ASTRIDE_B);
                }
                uint32_t b[8][2];
#pragma unroll
                for (int nj = 0; nj < 8; nj++) {
                    uint32_t bd = st + bLds0 + (uint32_t)(nj * 8 * ASTRIDE_B + s * 32);
                    LDS64(b[nj][0], b[nj][1], bd);
                }
#pragma unroll
                for (int mi = 0; mi < 4; mi++)
#pragma unroll
                    for (int nj = 0; nj < 8; nj++)
                        MMA_F16(acc[mi][nj], a[mi], b[nj]);
            }
            __syncthreads();
        }

        // ---- Phase A: subtract e_half in place, per-row running max ----
#pragma unroll
        for (int mi = 0; mi < 4; mi++)
#pragma unroll
            for (int qh = 0; qh < 2; qh++) {
                const int r = wm * 64 + mi * 16 + g + 8 * qh;
                float m = -3.4e38f;
#pragma unroll
                for (int nj = 0; nj < 8; nj++) {
                    const int n = n0 + wn * 64 + nj * 8 + 2 * t;
                    acc[mi][nj][2 * qh]     -= ehs[n];
                    acc[mi][nj][2 * qh + 1] -= ehs[n + 1];
                    m = fmaxf(m, fmaxf(acc[mi][nj][2 * qh], acc[mi][nj][2 * qh + 1]));
                }
                atomicMax(&sMax[r], fenc(m));
            }
        __syncthreads();

        // ---- Phase B: collect candidates within certified margin of running max ----
#pragma unroll
        for (int mi = 0; mi < 4; mi++)
#pragma unroll
            for (int qh = 0; qh < 2; qh++) {
                const int r = wm * 64 + mi * 16 + g + 8 * qh;
                const float thr = fdec(sMax[r])
                                - (0.002f * sqrtf(sXsq[r] * maxEsq) + 0.03f);
#pragma unroll
                for (int nj = 0; nj < 8; nj++) {
                    const int n = n0 + wn * 64 + nj * 8 + 2 * t;
                    if (acc[mi][nj][2 * qh] >= thr) {
                        int p = atomicAdd(&sCnt[r], 1);
                        if (p < CAP) sList[r * CAP + p] = n;
                    }
                    if (acc[mi][nj][2 * qh + 1] >= thr) {
                        int p = atomicAdd(&sCnt[r], 1);
                        if (p < CAP) sList[r * CAP + p] = n + 1;
                    }
                }
            }
        __syncthreads();
    }

    // ---- write candidate lists to global (tiny) ----
    if (tid < BM) g_cnt[row0 + tid] = sCnt[tid];
    for (int i = tid; i < BM * CAP; i += 256) g_list[row0 * CAP + i] = sList[i];
}

// ---- pass 2: one warp per row, high occupancy hides fp64 latency ----
__global__ __launch_bounds__(256)
void rescue(const float* __restrict__ X, const float* __restrict__ E,
            float* __restrict__ out) {
    const int lane = threadIdx.x & 31;
    const int row  = blockIdx.x * 8 + (threadIdx.x >> 5);

    const float4* X4 = reinterpret_cast<const float4*>(X + (size_t)row * D);
    float4 x0 = X4[lane], x1 = X4[lane + 32];

    const int cnt = g_cnt[row];
    const bool fallback = (cnt > CAP);
    const int total = fallback ? NCODES : cnt;

    double bestv = -1e300;
    int    besti = NCODES;
    for (int c = 0; c < total; c++) {
        const int idx = fallback ? c : g_list[row * CAP + c];
        const float4* E4r = reinterpret_cast<const float4*>(E + (size_t)idx * D);
        float4 e0 = E4r[lane], e1 = E4r[lane + 32];
        double sc =
              (double)x0.x * e0.x + (double)x0.y * e0.y
            + (double)x0.z * e0.z + (double)x0.w * e0.w
            + (double)x1.x * e1.x + (double)x1.y * e1.y
            + (double)x1.z * e1.z + (double)x1.w * e1.w
            - 0.5 * ((double)e0.x * e0.x + (double)e0.y * e0.y
                   + (double)e0.z * e0.z + (double)e0.w * e0.w
                   + (double)e1.x * e1.x + (double)e1.y * e1.y
                   + (double)e1.z * e1.z + (double)e1.w * e1.w);
#pragma unroll
        for (int off = 16; off > 0; off >>= 1)
            sc += __shfl_xor_sync(0xffffffffu, sc, off);
        if (sc > bestv || (sc == bestv && idx < besti)) { bestv = sc; besti = idx; }
    }

    const float4* Eb = reinterpret_cast<const float4*>(E + (size_t)besti * D);
    float4* O4 = reinterpret_cast<float4*>(out + (size_t)row * D);
    O4[lane]      = Eb[lane];
    O4[lane + 32] = Eb[lane + 32];
}

extern "C" void kernel_launch(void* const* d_in, const int* in_sizes, int n_in,
                              void* d_out, int out_size) {
    const float* x = (const float*)d_in[0];     // [16,1024,256] f32
    const float* E = (const float*)d_in[1];     // [1024,256]    f32
    float* out = (float*)d_out;

    init_kernel<<<1, 1>>>();
    prep_e<<<NCODES * 16 / 256, 256>>>(E);
    prep_x<<<ROWS_TOTAL * 16 / 256, 256>>>(x);

    cudaFuncSetAttribute(vq_mma, cudaFuncAttributeMaxDynamicSharedMemorySize, SMEM_TOTAL);
    vq_mma<<<ROWS_TOTAL / BM, 256, SMEM_TOTAL>>>();

    rescue<<<ROWS_TOTAL / 8, 256>>>(x, E, out);
}

// round 10
// speedup vs baseline: 2.4879x; 2.2345x over previous
#include <cuda_runtime.h>
#include <cuda_fp16.h>
#include <cstdint>

#define D          256
#define NCODES     1024
#define ROWS_TOTAL 16384
#define BM         128
#define BN         256
#define NKCH       4         // K=256, chunks of 64
#define NITER      4         // NCODES / BN
#define CAP        16        // candidate list capacity per row

#define ASTRIDE_B   160
#define A_STAGE     (BM * ASTRIDE_B)              // 20480
#define B_STAGE     (BN * ASTRIDE_B)              // 40960
#define STAGE_BYTES (A_STAGE + B_STAGE)           // 61440
#define B_OFF       A_STAGE
#define EHALF_OFF   (2 * STAGE_BYTES)             // 122880
#define XSQ_OFF     (EHALF_OFF + NCODES * 4)      // 126976
#define SMAX_OFF    (XSQ_OFF + BM * 4)            // 127488
#define SCNT_OFF    (SMAX_OFF + BM * 4)           // 128000
#define SLIST_OFF   (SCNT_OFF + BM * 4)           // 128512
#define SMEM_TOTAL  (SLIST_OFF + BM * CAP * 4)    // 136704

__device__ __half g_Xc[(size_t)ROWS_TOTAL * D];    // 8 MB  (fp16 hi, mma-interleaved)
__device__ __half g_Ec[(size_t)NCODES * D];        // 0.5 MB
__device__ float  g_e_half[NCODES];
__device__ float  g_xsq[ROWS_TOTAL];
__device__ int    g_maxEsq_bits;                   // atomicMax idempotent across replays
__device__ int    g_cnt[ROWS_TOTAL];
__device__ int    g_list[ROWS_TOTAL * CAP];

__device__ __forceinline__ constexpr int ilv16(int k) {
    return 4 * ((k & 7) >> 1) + 2 * (k >> 3) + (k & 1);
}
__device__ __forceinline__ unsigned fenc(float f) {
    unsigned u = __float_as_uint(f);
    return (u & 0x80000000u) ? ~u : (u | 0x80000000u);
}
__device__ __forceinline__ float fdec(unsigned u) {
    return __uint_as_float((u & 0x80000000u) ? (u ^ 0x80000000u) : ~u);
}

__global__ void prep_x(const float* __restrict__ X) {
    int gi = blockIdx.x * blockDim.x + threadIdx.x;
    const float4* src = reinterpret_cast<const float4*>(X) + (size_t)gi * 4;
    float4 v0 = src[0], v1 = src[1], v2 = src[2], v3 = src[3];
    float f[16] = { v0.x, v0.y, v0.z, v0.w, v1.x, v1.y, v1.z, v1.w,
                    v2.x, v2.y, v2.z, v2.w, v3.x, v3.y, v3.z, v3.w };
    __half h[16];
    float s = 0.f;
#pragma unroll
    for (int j = 0; j < 16; j++) { h[ilv16(j)] = __float2half_rn(f[j]); s += f[j] * f[j]; }
    uint4* dst = reinterpret_cast<uint4*>(g_Xc) + (size_t)gi * 2;
    dst[0] = reinterpret_cast<const uint4*>(h)[0];
    dst[1] = reinterpret_cast<const uint4*>(h)[1];
#pragma unroll
    for (int off = 8; off > 0; off >>= 1)
        s += __shfl_down_sync(0xffffffffu, s, off, 16);
    if ((gi & 15) == 0) g_xsq[gi >> 4] = s;
}

__global__ void prep_e(const float* __restrict__ E) {
    int gi = blockIdx.x * blockDim.x + threadIdx.x;
    const float4* src = reinterpret_cast<const float4*>(E) + (size_t)gi * 4;
    float4 v0 = src[0], v1 = src[1], v2 = src[2], v3 = src[3];
    float f[16] = { v0.x, v0.y, v0.z, v0.w, v1.x, v1.y, v1.z, v1.w,
                    v2.x, v2.y, v2.z, v2.w, v3.x, v3.y, v3.z, v3.w };
    __half h[16];
    float s = 0.f;
#pragma unroll
    for (int j = 0; j < 16; j++) { h[ilv16(j)] = __float2half_rn(f[j]); s += f[j] * f[j]; }
    uint4* dst = reinterpret_cast<uint4*>(g_Ec) + (size_t)gi * 2;
    dst[0] = reinterpret_cast<const uint4*>(h)[0];
    dst[1] = reinterpret_cast<const uint4*>(h)[1];
#pragma unroll
    for (int off = 8; off > 0; off >>= 1)
        s += __shfl_down_sync(0xffffffffu, s, off, 16);
    if ((gi & 15) == 0) {
        g_e_half[gi >> 4] = 0.5f * s;
        atomicMax(&g_maxEsq_bits, __float_as_int(s));
    }
}

static __device__ __forceinline__ uint32_t smem_u32(const void* p) {
    uint32_t a;
    asm("{ .reg .u64 t; cvta.to.shared.u64 t, %1; cvt.u32.u64 %0, t; }" : "=r"(a) : "l"(p));
    return a;
}
#define CP16(dst, src) asm volatile("cp.async.cg.shared.global [%0], [%1], 16;" :: "r"(dst), "l"(src) : "memory")
#define LDS64(r0, r1, a) asm volatile("ld.shared.v2.b32 {%0,%1}, [%2];" : "=r"(r0), "=r"(r1) : "r"(a))
#define MMA_F16(c, a, b) \
    asm volatile("mma.sync.aligned.m16n8k16.row.col.f32.f16.f16.f32 " \
                 "{%0,%1,%2,%3}, {%4,%5,%6,%7}, {%8,%9}, {%0,%1,%2,%3};" \
                 : "+f"((c)[0]), "+f"((c)[1]), "+f"((c)[2]), "+f"((c)[3]) \
                 : "r"((a)[0]), "r"((a)[1]), "r"((a)[2]), "r"((a)[3]), "r"((b)[0]), "r"((b)[1]))

__global__ __launch_bounds__(256, 1)
void vq_mma() {
    extern __shared__ char smem[];
    const uint32_t sb = smem_u32(smem);
    float*    ehs   = (float*)(smem + EHALF_OFF);
    float*    sXsq  = (float*)(smem + XSQ_OFF);
    unsigned* sMax  = (unsigned*)(smem + SMAX_OFF);
    int*      sCnt  = (int*)(smem + SCNT_OFF);
    int*      sList = (int*)(smem + SLIST_OFF);

    const int tid  = threadIdx.x;
    const int lane = tid & 31, wid = tid >> 5;
    const int wm = wid & 1, wn = wid >> 1;
    const int g = lane >> 2, t = lane & 3;
    const int row0 = blockIdx.x * BM;
    const float maxEsq = __int_as_float(g_maxEsq_bits);

    for (int i = tid; i < NCODES; i += 256) ehs[i] = g_e_half[i];
    if (tid < BM) {
        sXsq[tid] = g_xsq[row0 + tid];
        sMax[tid] = 0u;
        sCnt[tid] = 0;
    }

    const int urow = tid >> 3, uj = tid & 7;
    const char* aSrc0 = (const char*)(g_Xc + (size_t)(row0 + urow) * D) + uj * 16;
    const uint32_t aDst0 = sb + urow * ASTRIDE_B + uj * 16;
    const uint32_t bDst0 = sb + B_OFF + urow * ASTRIDE_B + uj * 16;
    const uint32_t aLds0 = sb + (uint32_t)((wm * 64 + g) * ASTRIDE_B + t * 8);
    const uint32_t bLds0 = sb + (uint32_t)(B_OFF + (wn * 64 + g) * ASTRIDE_B + t * 8);
    __syncthreads();

    for (int ni = 0; ni < NITER; ni++) {
        const int n0 = ni * BN;
        const char* bSrc0 = (const char*)(g_Ec + (size_t)(n0 + urow) * D) + uj * 16;

        float acc[4][8][4];
#pragma unroll
        for (int mi = 0; mi < 4; mi++)
#pragma unroll
            for (int nj = 0; nj < 8; nj++)
#pragma unroll
                for (int q = 0; q < 4; q++) acc[mi][nj][q] = 0.f;

        {
#pragma unroll
            for (int i = 0; i < 4; i++) CP16(aDst0 + i * (32 * ASTRIDE_B), aSrc0 + i * 16384);
#pragma unroll
            for (int i = 0; i < 8; i++) CP16(bDst0 + i * (32 * ASTRIDE_B), bSrc0 + i * 16384);
            asm volatile("cp.async.commit_group;" ::: "memory");
        }

        for (int kc = 0; kc < NKCH; kc++) {
            const uint32_t st = (uint32_t)(kc & 1) * STAGE_BYTES;

            if (kc + 1 < NKCH) {
                const int kn = kc + 1;
                const uint32_t nst = (uint32_t)(kn & 1) * STAGE_BYTES;
#pragma unroll
                for (int i = 0; i < 4; i++)
                    CP16(nst + aDst0 + i * (32 * ASTRIDE_B), aSrc0 + kn * 128 + i * 16384);
#pragma unroll
                for (int i = 0; i < 8; i++)
                    CP16(nst + bDst0 + i * (32 * ASTRIDE_B), bSrc0 + kn * 128 + i * 16384);
                asm volatile("cp.async.commit_group;" ::: "memory");
                asm volatile("cp.async.wait_group 1;" ::: "memory");
            } else {
                asm volatile("cp.async.wait_group 0;" ::: "memory");
            }
            __syncthreads();

#pragma unroll
            for (int s = 0; s < 4; s++) {
                uint32_t a[4][4];
#pragma unroll
                for (int mi = 0; mi < 4; mi++) {
                    uint32_t ad = st + aLds0 + (uint32_t)(mi * 16 * ASTRIDE_B + s * 32);
                    LDS64(a[mi][0], a[mi][2], ad);
                    LDS64(a[mi][1], a[mi][3], ad + 8 * ASTRIDE_B);
                }
                uint32_t b[8][2];
#pragma unroll
                for (int nj = 0; nj < 8; nj++) {
                    uint32_t bd = st + bLds0 + (uint32_t)(nj * 8 * ASTRIDE_B + s * 32);
                    LDS64(b[nj][0], b[nj][1], bd);
                }
#pragma unroll
                for (int mi = 0; mi < 4; mi++)
#pragma unroll
                    for (int nj = 0; nj < 8; nj++)
                        MMA_F16(acc[mi][nj], a[mi], b[nj]);
            }
            __syncthreads();
        }

        // ---- Phase A: subtract e_half, per-row running max ----
#pragma unroll
        for (int mi = 0; mi < 4; mi++)
#pragma unroll
            for (int qh = 0; qh < 2; qh++) {
                const int r = wm * 64 + mi * 16 + g + 8 * qh;
                float m = -3.4e38f;
#pragma unroll
                for (int nj = 0; nj < 8; nj++) {
                    const int n = n0 + wn * 64 + nj * 8 + 2 * t;
                    acc[mi][nj][2 * qh]     -= ehs[n];
                    acc[mi][nj][2 * qh + 1] -= ehs[n + 1];
                    m = fmaxf(m, fmaxf(acc[mi][nj][2 * qh], acc[mi][nj][2 * qh + 1]));
                }
                atomicMax(&sMax[r], fenc(m));
            }
        __syncthreads();

        // ---- Phase B: collect candidates within certified margin ----
#pragma unroll
        for (int mi = 0; mi < 4; mi++)
#pragma unroll
            for (int qh = 0; qh < 2; qh++) {
                const int r = wm * 64 + mi * 16 + g + 8 * qh;
                const float thr = fdec(sMax[r])
                                - (0.002f * sqrtf(sXsq[r] * maxEsq) + 0.03f);
#pragma unroll
                for (int nj = 0; nj < 8; nj++) {
                    const int n = n0 + wn * 64 + nj * 8 + 2 * t;
                    if (acc[mi][nj][2 * qh] >= thr) {
                        int p = atomicAdd(&sCnt[r], 1);
                        if (p < CAP) sList[r * CAP + p] = n;
                    }
                    if (acc[mi][nj][2 * qh + 1] >= thr) {
                        int p = atomicAdd(&sCnt[r], 1);
                        if (p < CAP) sList[r * CAP + p] = n + 1;
                    }
                }
            }
        __syncthreads();
    }

    if (tid < BM) g_cnt[row0 + tid] = sCnt[tid];
    for (int i = tid; i < BM * CAP; i += 256) g_list[row0 * CAP + i] = sList[i];
}

// ---- double-float helpers (fp32 pipe; FP64 is fused-off on B300) ----
__device__ __forceinline__ void df_renorm(float& h, float& l) {
    float s = h + l;
    l = l - (s - h);
    h = s;
}
__device__ __forceinline__ void df_add(float& ah, float& al, float bh, float bl) {
    float s = ah + bh;
    float v = s - ah;
    float e = (ah - (s - v)) + (bh - v);
    float l = e + al + bl;
    ah = s; al = l;
    df_renorm(ah, al);
}

// ---- pass 2: one warp per row, compensated-fp32 exact rescore ----
__global__ __launch_bounds__(256)
void rescue(const float* __restrict__ X, const float* __restrict__ E,
            float* __restrict__ out) {
    const int lane = threadIdx.x & 31;
    const int row  = blockIdx.x * 8 + (threadIdx.x >> 5);

    const float4* X4 = reinterpret_cast<const float4*>(X + (size_t)row * D);
    float4 x0 = X4[lane], x1 = X4[lane + 32];
    const float xv[8] = { x0.x, x0.y, x0.z, x0.w, x1.x, x1.y, x1.z, x1.w };

    const int cnt = g_cnt[row];
    const bool fallback = (cnt > CAP);
    const int total = fallback ? NCODES : cnt;

    float bh = -3.4e38f, bl = 0.f;
    int   besti = NCODES;
    for (int c = 0; c < total; c++) {
        const int idx = fallback ? c : g_list[row * CAP + c];
        const float4* E4r = reinterpret_cast<const float4*>(E + (size_t)idx * D);
        float4 e0 = E4r[lane], e1 = E4r[lane + 32];
        const float ev[8] = { e0.x, e0.y, e0.z, e0.w, e1.x, e1.y, e1.z, e1.w };

        // per-lane compensated sum of e*(x - 0.5e)
        float s = 0.f, comp = 0.f;
#pragma unroll
        for (int j = 0; j < 8; j++) {
            float p    = fmaf(-0.5f, ev[j], xv[j]);     // x - e/2
            float prod = ev[j] * p;
            float perr = fmaf(ev[j], p, -prod);          // exact product error
            float tsum = s + prod;                       // Knuth TwoSum
            float v    = tsum - s;
            float serr = (s - (tsum - v)) + (prod - v);
            s = tsum;
            comp += serr + perr;
        }
        float h = s, l = comp;
        df_renorm(h, l);

        // warp reduction of (h,l) pairs — deterministic xor tree
#pragma unroll
        for (int off = 16; off > 0; off >>= 1) {
            float oh = __shfl_xor_sync(0xffffffffu, h, off);
            float ol = __shfl_xor_sync(0xffffffffu, l, off);
            df_add(h, l, oh, ol);
        }

        bool gt = (h > bh) || (h == bh && l > bl);
        bool eq = (h == bh) && (l == bl);
        if (gt || (eq && idx < besti)) { bh = h; bl = l; besti = idx; }
    }

    const float4* Eb = reinterpret_cast<const float4*>(E + (size_t)besti * D);
    float4* O4 = reinterpret_cast<float4*>(out + (size_t)row * D);
    O4[lane]      = Eb[lane];
    O4[lane + 32] = Eb[lane + 32];
}

extern "C" void kernel_launch(void* const* d_in, const int* in_sizes, int n_in,
                              void* d_out, int out_size) {
    const float* x = (const float*)d_in[0];     // [16,1024,256] f32
    const float* E = (const float*)d_in[1];     // [1024,256]    f32
    float* out = (float*)d_out;

    prep_e<<<NCODES * 16 / 256, 256>>>(E);
    prep_x<<<ROWS_TOTAL * 16 / 256, 256>>>(x);

    cudaFuncSetAttribute(vq_mma, cudaFuncAttributeMaxDynamicSharedMemorySize, SMEM_TOTAL);
    vq_mma<<<ROWS_TOTAL / BM, 256, SMEM_TOTAL>>>();

    rescue<<<ROWS_TOTAL / 8, 256>>>(x, E, out);
}

// round 11
// speedup vs baseline: 2.4951x; 1.0029x over previous
#include <cuda_runtime.h>
#include <cuda_fp16.h>
#include <cstdint>

#define D          256
#define NCODES     1024
#define ROWS_TOTAL 16384
#define BM         128
#define BN         256
#define NCHUNK     16        // flat: 4 n-chunks x 4 k-chunks of 64
#define CAP        24        // candidate list capacity per row

#define ASTRIDE_B   160
#define A_STAGE     (BM * ASTRIDE_B)              // 20480
#define B_STAGE     (BN * ASTRIDE_B)              // 40960
#define STAGE_BYTES (A_STAGE + B_STAGE)           // 61440
#define B_OFF       A_STAGE
#define EHALF_OFF   (3 * STAGE_BYTES)             // 184320 (3-stage pipeline)
#define XSQ_OFF     (EHALF_OFF + NCODES * 4)      // 188416
#define SMAX_OFF    (XSQ_OFF + BM * 4)            // 188928
#define SCNT_OFF    (SMAX_OFF + BM * 4)           // 189440
#define SLIST_OFF   (SCNT_OFF + BM * 4)           // 189952
#define SMEM_TOTAL  (SLIST_OFF + BM * CAP * 4)    // 202240

__device__ __half g_Xc[(size_t)ROWS_TOTAL * D];    // 8 MB  (fp16 hi, mma-interleaved)
__device__ __half g_Ec[(size_t)NCODES * D];        // 0.5 MB
__device__ float  g_e_half[NCODES];
__device__ float  g_xsq[ROWS_TOTAL];
__device__ int    g_maxEsq_bits;                   // atomicMax idempotent across replays
__device__ int    g_cnt[ROWS_TOTAL];
__device__ int    g_list[ROWS_TOTAL * CAP];

__device__ __forceinline__ constexpr int ilv16(int k) {
    return 4 * ((k & 7) >> 1) + 2 * (k >> 3) + (k & 1);
}
__device__ __forceinline__ unsigned fenc(float f) {
    unsigned u = __float_as_uint(f);
    return (u & 0x80000000u) ? ~u : (u | 0x80000000u);
}
__device__ __forceinline__ float fdec(unsigned u) {
    return __uint_as_float((u & 0x80000000u) ? (u ^ 0x80000000u) : ~u);
}

__global__ void prep_x(const float* __restrict__ X) {
    int gi = blockIdx.x * blockDim.x + threadIdx.x;
    const float4* src = reinterpret_cast<const float4*>(X) + (size_t)gi * 4;
    float4 v0 = src[0], v1 = src[1], v2 = src[2], v3 = src[3];
    float f[16] = { v0.x, v0.y, v0.z, v0.w, v1.x, v1.y, v1.z, v1.w,
                    v2.x, v2.y, v2.z, v2.w, v3.x, v3.y, v3.z, v3.w };
    __half h[16];
    float s = 0.f;
#pragma unroll
    for (int j = 0; j < 16; j++) { h[ilv16(j)] = __float2half_rn(f[j]); s += f[j] * f[j]; }
    uint4* dst = reinterpret_cast<uint4*>(g_Xc) + (size_t)gi * 2;
    dst[0] = reinterpret_cast<const uint4*>(h)[0];
    dst[1] = reinterpret_cast<const uint4*>(h)[1];
#pragma unroll
    for (int off = 8; off > 0; off >>= 1)
        s += __shfl_down_sync(0xffffffffu, s, off, 16);
    if ((gi & 15) == 0) g_xsq[gi >> 4] = s;
}

__global__ void prep_e(const float* __restrict__ E) {
    int gi = blockIdx.x * blockDim.x + threadIdx.x;
    const float4* src = reinterpret_cast<const float4*>(E) + (size_t)gi * 4;
    float4 v0 = src[0], v1 = src[1], v2 = src[2], v3 = src[3];
    float f[16] = { v0.x, v0.y, v0.z, v0.w, v1.x, v1.y, v1.z, v1.w,
                    v2.x, v2.y, v2.z, v2.w, v3.x, v3.y, v3.z, v3.w };
    __half h[16];
    float s = 0.f;
#pragma unroll
    for (int j = 0; j < 16; j++) { h[ilv16(j)] = __float2half_rn(f[j]); s += f[j] * f[j]; }
    uint4* dst = reinterpret_cast<uint4*>(g_Ec) + (size_t)gi * 2;
    dst[0] = reinterpret_cast<const uint4*>(h)[0];
    dst[1] = reinterpret_cast<const uint4*>(h)[1];
#pragma unroll
    for (int off = 8; off > 0; off >>= 1)
        s += __shfl_down_sync(0xffffffffu, s, off, 16);
    if ((gi & 15) == 0) {
        g_e_half[gi >> 4] = 0.5f * s;
        atomicMax(&g_maxEsq_bits, __float_as_int(s));
    }
}

static __device__ __forceinline__ uint32_t smem_u32(const void* p) {
    uint32_t a;
    asm("{ .reg .u64 t; cvta.to.shared.u64 t, %1; cvt.u32.u64 %0, t; }" : "=r"(a) : "l"(p));
    return a;
}
#define CP16(dst, src) asm volatile("cp.async.cg.shared.global [%0], [%1], 16;" :: "r"(dst), "l"(src) : "memory")
#define LDS64(r0, r1, a) asm volatile("ld.shared.v2.b32 {%0,%1}, [%2];" : "=r"(r0), "=r"(r1) : "r"(a))
#define MMA_F16(c, a, b) \
    asm volatile("mma.sync.aligned.m16n8k16.row.col.f32.f16.f16.f32 " \
                 "{%0,%1,%2,%3}, {%4,%5,%6,%7}, {%8,%9}, {%0,%1,%2,%3};" \
                 : "+f"((c)[0]), "+f"((c)[1]), "+f"((c)[2]), "+f"((c)[3]) \
                 : "r"((a)[0]), "r"((a)[1]), "r"((a)[2]), "r"((a)[3]), "r"((b)[0]), "r"((b)[1]))

__global__ __launch_bounds__(256, 1)
void vq_mma() {
    extern __shared__ char smem[];
    const uint32_t sb = smem_u32(smem);
    float*    ehs   = (float*)(smem + EHALF_OFF);
    float*    sXsq  = (float*)(smem + XSQ_OFF);
    unsigned* sMax  = (unsigned*)(smem + SMAX_OFF);
    int*      sCnt  = (int*)(smem + SCNT_OFF);
    int*      sList = (int*)(smem + SLIST_OFF);

    const int tid  = threadIdx.x;
    const int lane = tid & 31, wid = tid >> 5;
    const int wm = wid & 1, wn = wid >> 1;
    const int g = lane >> 2, t = lane & 3;
    const int row0 = blockIdx.x * BM;
    const float maxEsq = __int_as_float(g_maxEsq_bits);

    for (int i = tid; i < NCODES; i += 256) ehs[i] = g_e_half[i];
    if (tid < BM) {
        sXsq[tid] = g_xsq[row0 + tid];
        sMax[tid] = 0u;
        sCnt[tid] = 0;
    }

    const int urow = tid >> 3, uj = tid & 7;
    const char* aSrcB = (const char*)(g_Xc + (size_t)(row0 + urow) * D) + uj * 16;
    const char* bSrcB = (const char*)(g_Ec + (size_t)urow * D) + uj * 16;
    const uint32_t aDst0 = sb + urow * ASTRIDE_B + uj * 16;
    const uint32_t bDst0 = sb + B_OFF + urow * ASTRIDE_B + uj * 16;
    const uint32_t aLds0 = sb + (uint32_t)((wm * 64 + g) * ASTRIDE_B + t * 8);
    const uint32_t bLds0 = sb + (uint32_t)(B_OFF + (wn * 64 + g) * ASTRIDE_B + t * 8);

    // chunk c: ni = c>>2 (n-block), kc = c&3 (k-block); stage = c % 3
#define ISSUE(c) do {                                                            \
        const uint32_t _st = (uint32_t)((c) % 3) * STAGE_BYTES;                  \
        const int _off = ((c) & 3) * 128;                                        \
        const int _boff = ((c) >> 2) * 131072 + _off;  /* ni*BN*512 */           \
        _Pragma("unroll")                                                        \
        for (int i = 0; i < 4; i++) CP16(_st + aDst0 + i * (32 * ASTRIDE_B),     \
                                         aSrcB + _off + i * 16384);              \
        _Pragma("unroll")                                                        \
        for (int i = 0; i < 8; i++) CP16(_st + bDst0 + i * (32 * ASTRIDE_B),     \
                                         bSrcB + _boff + i * 16384);             \
        asm volatile("cp.async.commit_group;" ::: "memory");                     \
    } while (0)

    ISSUE(0);
    ISSUE(1);

    float acc[4][8][4];
#pragma unroll
    for (int mi = 0; mi < 4; mi++)
#pragma unroll
        for (int nj = 0; nj < 8; nj++)
#pragma unroll
            for (int q = 0; q < 4; q++) acc[mi][nj][q] = 0.f;

    __syncthreads();   // covers smem init + makes barrier pattern uniform

#pragma unroll 1
    for (int c = 0; c < NCHUNK; c++) {
        if (c <= NCHUNK - 3) {
            ISSUE(c + 2);
            asm volatile("cp.async.wait_group 2;" ::: "memory");
        } else if (c == NCHUNK - 2) {
            asm volatile("cp.async.wait_group 1;" ::: "memory");
        } else {
            asm volatile("cp.async.wait_group 0;" ::: "memory");
        }
        __syncthreads();                         // stage c filled, visible to all

        const uint32_t st = (uint32_t)(c % 3) * STAGE_BYTES;
#pragma unroll
        for (int s = 0; s < 4; s++) {
            uint32_t a[4][4];
#pragma unroll
            for (int mi = 0; mi < 4; mi++) {
                uint32_t ad = st + aLds0 + (uint32_t)(mi * 16 * ASTRIDE_B + s * 32);
                LDS64(a[mi][0], a[mi][2], ad);
                LDS64(a[mi][1], a[mi][3], ad + 8 * ASTRIDE_B);
            }
            uint32_t b[8][2];
#pragma unroll
            for (int nj = 0; nj < 8; nj++) {
                uint32_t bd = st + bLds0 + (uint32_t)(nj * 8 * ASTRIDE_B + s * 32);
                LDS64(b[nj][0], b[nj][1], bd);
            }
#pragma unroll
            for (int mi = 0; mi < 4; mi++)
#pragma unroll
                for (int nj = 0; nj < 8; nj++)
                    MMA_F16(acc[mi][nj], a[mi], b[nj]);
        }

        if ((c & 3) == 3) {                      // end of an n-chunk: phases (no barriers)
            const int n0 = (c >> 2) * BN;
            // Phase A: subtract e_half, per-row max with shuffle pre-reduction
#pragma unroll
            for (int mi = 0; mi < 4; mi++)
#pragma unroll
                for (int qh = 0; qh < 2; qh++) {
                    const int r = wm * 64 + mi * 16 + g + 8 * qh;
                    float m = -3.4e38f;
#pragma unroll
                    for (int nj = 0; nj < 8; nj++) {
                        const int n = n0 + wn * 64 + nj * 8 + 2 * t;
                        acc[mi][nj][2 * qh]     -= ehs[n];
                        acc[mi][nj][2 * qh + 1] -= ehs[n + 1];
                        m = fmaxf(m, fmaxf(acc[mi][nj][2 * qh], acc[mi][nj][2 * qh + 1]));
                    }
                    m = fmaxf(m, __shfl_xor_sync(0xffffffffu, m, 1));
                    m = fmaxf(m, __shfl_xor_sync(0xffffffffu, m, 2));
                    if (t == 0) atomicMax(&sMax[r], fenc(m));
                }
            // Phase B: candidates vs current running max (monotone => certified superset)
#pragma unroll
            for (int mi = 0; mi < 4; mi++)
#pragma unroll
                for (int qh = 0; qh < 2; qh++) {
                    const int r = wm * 64 + mi * 16 + g + 8 * qh;
                    const float thr = fdec(sMax[r])
                                    - (0.002f * sqrtf(sXsq[r] * maxEsq) + 0.03f);
#pragma unroll
                    for (int nj = 0; nj < 8; nj++) {
                        const int n = n0 + wn * 64 + nj * 8 + 2 * t;
                        if (acc[mi][nj][2 * qh] >= thr) {
                            int p = atomicAdd(&sCnt[r], 1);
                            if (p < CAP) sList[r * CAP + p] = n;
                        }
                        if (acc[mi][nj][2 * qh + 1] >= thr) {
                            int p = atomicAdd(&sCnt[r], 1);
                            if (p < CAP) sList[r * CAP + p] = n + 1;
                        }
                    }
                }
            // reset accumulators for next n-chunk
#pragma unroll
            for (int mi = 0; mi < 4; mi++)
#pragma unroll
                for (int nj = 0; nj < 8; nj++)
#pragma unroll
                    for (int q = 0; q < 4; q++) acc[mi][nj][q] = 0.f;
        }
        __syncthreads();                         // compute(c) done before stage reuse
    }

    if (tid < BM) g_cnt[row0 + tid] = sCnt[tid];
    for (int i = tid; i < BM * CAP; i += 256) g_list[row0 * CAP + i] = sList[i];
#undef ISSUE
}

// ---- double-float helpers (fp32 pipe; FP64 is fused-off on B300) ----
__device__ __forceinline__ void df_renorm(float& h, float& l) {
    float s = h + l;
    l = l - (s - h);
    h = s;
}
__device__ __forceinline__ void df_add(float& ah, float& al, float bh, float bl) {
    float s = ah + bh;
    float v = s - ah;
    float e = (ah - (s - v)) + (bh - v);
    float l = e + al + bl;
    ah = s; al = l;
    df_renorm(ah, al);
}

__global__ __launch_bounds__(256)
void rescue(const float* __restrict__ X, const float* __restrict__ E,
            float* __restrict__ out) {
    const int lane = threadIdx.x & 31;
    const int row  = blockIdx.x * 8 + (threadIdx.x >> 5);

    const float4* X4 = reinterpret_cast<const float4*>(X + (size_t)row * D);
    float4 x0 = X4[lane], x1 = X4[lane + 32];
    const float xv[8] = { x0.x, x0.y, x0.z, x0.w, x1.x, x1.y, x1.z, x1.w };

    const int cnt = g_cnt[row];
    const bool fallback = (cnt > CAP);
    const int total = fallback ? NCODES : cnt;

    float bh = -3.4e38f, bl = 0.f;
    int   besti = NCODES;
    for (int c = 0; c < total; c++) {
        const int idx = fallback ? c : g_list[row * CAP + c];
        const float4* E4r = reinterpret_cast<const float4*>(E + (size_t)idx * D);
        float4 e0 = E4r[lane], e1 = E4r[lane + 32];
        const float ev[8] = { e0.x, e0.y, e0.z, e0.w, e1.x, e1.y, e1.z, e1.w };

        float s = 0.f, comp = 0.f;
#pragma unroll
        for (int j = 0; j < 8; j++) {
            float p    = fmaf(-0.5f, ev[j], xv[j]);
            float prod = ev[j] * p;
            float perr = fmaf(ev[j], p, -prod);
            float tsum = s + prod;
            float v    = tsum - s;
            float serr = (s - (tsum - v)) + (prod - v);
            s = tsum;
            comp += serr + perr;
        }
        float h = s, l = comp;
        df_renorm(h, l);
#pragma unroll
        for (int off = 16; off > 0; off >>= 1) {
            float oh = __shfl_xor_sync(0xffffffffu, h, off);
            float ol = __shfl_xor_sync(0xffffffffu, l, off);
            df_add(h, l, oh, ol);
        }

        bool gt = (h > bh) || (h == bh && l > bl);
        bool eq = (h == bh) && (l == bl);
        if (gt || (eq && idx < besti)) { bh = h; bl = l; besti = idx; }
    }

    const float4* Eb = reinterpret_cast<const float4*>(E + (size_t)besti * D);
    float4* O4 = reinterpret_cast<float4*>(out + (size_t)row * D);
    O4[lane]      = Eb[lane];
    O4[lane + 32] = Eb[lane + 32];
}

extern "C" void kernel_launch(void* const* d_in, const int* in_sizes, int n_in,
                              void* d_out, int out_size) {
    const float* x = (const float*)d_in[0];     // [16,1024,256] f32
    const float* E = (const float*)d_in[1];     // [1024,256]    f32
    float* out = (float*)d_out;

    prep_e<<<NCODES * 16 / 256, 256>>>(E);
    prep_x<<<ROWS_TOTAL * 16 / 256, 256>>>(x);

    cudaFuncSetAttribute(vq_mma, cudaFuncAttributeMaxDynamicSharedMemorySize, SMEM_TOTAL);
    vq_mma<<<ROWS_TOTAL / BM, 256, SMEM_TOTAL>>>();

    rescue<<<ROWS_TOTAL / 8, 256>>>(x, E, out);
}

// round 12
// speedup vs baseline: 2.6092x; 1.0457x over previous
#include <cuda_runtime.h>
#include <cuda_fp16.h>
#include <cstdint>

#define D          256
#define NCODES     1024
#define ROWS_TOTAL 16384
#define BM         128
#define BN         256
#define NCHUNK     16        // flat: 4 n-chunks x 4 k-chunks of 64
#define CAP        24        // candidate list capacity per row
#define NT         512       // threads per CTA

#define ASTRIDE_B   160
#define A_STAGE     (BM * ASTRIDE_B)              // 20480
#define B_STAGE     (BN * ASTRIDE_B)              // 40960
#define STAGE_BYTES (A_STAGE + B_STAGE)           // 61440
#define B_OFF       A_STAGE
#define EHALF_OFF   (3 * STAGE_BYTES)             // 184320 (3-stage pipeline)
#define XSQ_OFF     (EHALF_OFF + NCODES * 4)      // 188416
#define SMAX_OFF    (XSQ_OFF + BM * 4)            // 188928
#define SCNT_OFF    (SMAX_OFF + BM * 4)           // 189440
#define SLIST_OFF   (SCNT_OFF + BM * 4)           // 189952
#define SMEM_TOTAL  (SLIST_OFF + BM * CAP * 4)    // 202240

__device__ __half g_Xc[(size_t)ROWS_TOTAL * D];    // 8 MB  (fp16 hi, mma-interleaved)
__device__ __half g_Ec[(size_t)NCODES * D];        // 0.5 MB
__device__ float  g_e_half[NCODES];
__device__ float  g_xsq[ROWS_TOTAL];
__device__ int    g_maxEsq_bits;                   // atomicMax idempotent across replays
__device__ int    g_cnt[ROWS_TOTAL];
__device__ int    g_list[ROWS_TOTAL * CAP];

__device__ __forceinline__ constexpr int ilv16(int k) {
    return 4 * ((k & 7) >> 1) + 2 * (k >> 3) + (k & 1);
}
__device__ __forceinline__ unsigned fenc(float f) {
    unsigned u = __float_as_uint(f);
    return (u & 0x80000000u) ? ~u : (u | 0x80000000u);
}
__device__ __forceinline__ float fdec(unsigned u) {
    return __uint_as_float((u & 0x80000000u) ? (u ^ 0x80000000u) : ~u);
}

__global__ void prep_x(const float* __restrict__ X) {
    int gi = blockIdx.x * blockDim.x + threadIdx.x;
    const float4* src = reinterpret_cast<const float4*>(X) + (size_t)gi * 4;
    float4 v0 = src[0], v1 = src[1], v2 = src[2], v3 = src[3];
    float f[16] = { v0.x, v0.y, v0.z, v0.w, v1.x, v1.y, v1.z, v1.w,
                    v2.x, v2.y, v2.z, v2.w, v3.x, v3.y, v3.z, v3.w };
    __half h[16];
    float s = 0.f;
#pragma unroll
    for (int j = 0; j < 16; j++) { h[ilv16(j)] = __float2half_rn(f[j]); s += f[j] * f[j]; }
    uint4* dst = reinterpret_cast<uint4*>(g_Xc) + (size_t)gi * 2;
    dst[0] = reinterpret_cast<const uint4*>(h)[0];
    dst[1] = reinterpret_cast<const uint4*>(h)[1];
#pragma unroll
    for (int off = 8; off > 0; off >>= 1)
        s += __shfl_down_sync(0xffffffffu, s, off, 16);
    if ((gi & 15) == 0) g_xsq[gi >> 4] = s;
}

__global__ void prep_e(const float* __restrict__ E) {
    int gi = blockIdx.x * blockDim.x + threadIdx.x;
    const float4* src = reinterpret_cast<const float4*>(E) + (size_t)gi * 4;
    float4 v0 = src[0], v1 = src[1], v2 = src[2], v3 = src[3];
    float f[16] = { v0.x, v0.y, v0.z, v0.w, v1.x, v1.y, v1.z, v1.w,
                    v2.x, v2.y, v2.z, v2.w, v3.x, v3.y, v3.z, v3.w };
    __half h[16];
    float s = 0.f;
#pragma unroll
    for (int j = 0; j < 16; j++) { h[ilv16(j)] = __float2half_rn(f[j]); s += f[j] * f[j]; }
    uint4* dst = reinterpret_cast<uint4*>(g_Ec) + (size_t)gi * 2;
    dst[0] = reinterpret_cast<const uint4*>(h)[0];
    dst[1] = reinterpret_cast<const uint4*>(h)[1];
#pragma unroll
    for (int off = 8; off > 0; off >>= 1)
        s += __shfl_down_sync(0xffffffffu, s, off, 16);
    if ((gi & 15) == 0) {
        g_e_half[gi >> 4] = 0.5f * s;
        atomicMax(&g_maxEsq_bits, __float_as_int(s));
    }
}

static __device__ __forceinline__ uint32_t smem_u32(const void* p) {
    uint32_t a;
    asm("{ .reg .u64 t; cvta.to.shared.u64 t, %1; cvt.u32.u64 %0, t; }" : "=r"(a) : "l"(p));
    return a;
}
#define CP16(dst, src) asm volatile("cp.async.cg.shared.global [%0], [%1], 16;" :: "r"(dst), "l"(src) : "memory")
#define LDS64(r0, r1, a) asm volatile("ld.shared.v2.b32 {%0,%1}, [%2];" : "=r"(r0), "=r"(r1) : "r"(a))
#define MMA_F16(c, a, b) \
    asm volatile("mma.sync.aligned.m16n8k16.row.col.f32.f16.f16.f32 " \
                 "{%0,%1,%2,%3}, {%4,%5,%6,%7}, {%8,%9}, {%0,%1,%2,%3};" \
                 : "+f"((c)[0]), "+f"((c)[1]), "+f"((c)[2]), "+f"((c)[3]) \
                 : "r"((a)[0]), "r"((a)[1]), "r"((a)[2]), "r"((a)[3]), "r"((b)[0]), "r"((b)[1]))

__global__ __launch_bounds__(NT, 1)
void vq_mma() {
    extern __shared__ char smem[];
    const uint32_t sb = smem_u32(smem);
    float*    ehs   = (float*)(smem + EHALF_OFF);
    float*    sXsq  = (float*)(smem + XSQ_OFF);
    unsigned* sMax  = (unsigned*)(smem + SMAX_OFF);
    int*      sCnt  = (int*)(smem + SCNT_OFF);
    int*      sList = (int*)(smem + SLIST_OFF);

    const int tid  = threadIdx.x;
    const int lane = tid & 31, wid = tid >> 5;          // 16 warps
    const int wm = wid & 3, wn = wid >> 2;              // 4(M) x 4(N)
    const int g = lane >> 2, t = lane & 3;
    const int row0 = blockIdx.x * BM;
    const float maxEsq = __int_as_float(g_maxEsq_bits);

    for (int i = tid; i < NCODES; i += NT) ehs[i] = g_e_half[i];
    if (tid < BM) {
        sXsq[tid] = g_xsq[row0 + tid];
        sMax[tid] = 0u;
        sCnt[tid] = 0;
    }

    // cp.async: 512 threads x 16B units. A: 2 units (rows urow, urow+64); B: 4 units.
    const int urow = tid >> 3, uj = tid & 7;            // urow 0..63
    const char* aSrcB = (const char*)(g_Xc + (size_t)(row0 + urow) * D) + uj * 16;
    const char* bSrcB = (const char*)(g_Ec + (size_t)urow * D) + uj * 16;
    const uint32_t aDst0 = sb + urow * ASTRIDE_B + uj * 16;
    const uint32_t bDst0 = sb + B_OFF + urow * ASTRIDE_B + uj * 16;
    const uint32_t aLds0 = sb + (uint32_t)((wm * 32 + g) * ASTRIDE_B + t * 8);
    const uint32_t bLds0 = sb + (uint32_t)(B_OFF + (wn * 64 + g) * ASTRIDE_B + t * 8);

    // chunk c: ni = c>>2 (n-block), kc = c&3 (k-block); stage = c % 3
#define ISSUE(c) do {                                                            \
        const uint32_t _st = (uint32_t)((c) % 3) * STAGE_BYTES;                  \
        const int _off = ((c) & 3) * 128;                                        \
        const int _boff = ((c) >> 2) * 131072 + _off;  /* ni*BN*512 */           \
        _Pragma("unroll")                                                        \
        for (int i = 0; i < 2; i++) CP16(_st + aDst0 + i * (64 * ASTRIDE_B),     \
                                         aSrcB + _off + i * 32768);              \
        _Pragma("unroll")                                                        \
        for (int i = 0; i < 4; i++) CP16(_st + bDst0 + i * (64 * ASTRIDE_B),     \
                                         bSrcB + _boff + i * 32768);             \
        asm volatile("cp.async.commit_group;" ::: "memory");                     \
    } while (0)

    ISSUE(0);
    ISSUE(1);

    float acc[2][8][4];
#pragma unroll
    for (int mi = 0; mi < 2; mi++)
#pragma unroll
        for (int nj = 0; nj < 8; nj++)
#pragma unroll
            for (int q = 0; q < 4; q++) acc[mi][nj][q] = 0.f;

    __syncthreads();

#pragma unroll 1
    for (int c = 0; c < NCHUNK; c++) {
        if (c <= NCHUNK - 3) {
            ISSUE(c + 2);
            asm volatile("cp.async.wait_group 2;" ::: "memory");
        } else if (c == NCHUNK - 2) {
            asm volatile("cp.async.wait_group 1;" ::: "memory");
        } else {
            asm volatile("cp.async.wait_group 0;" ::: "memory");
        }
        __syncthreads();

        const uint32_t st = (uint32_t)(c % 3) * STAGE_BYTES;
#pragma unroll
        for (int s = 0; s < 4; s++) {
            uint32_t a[2][4];
#pragma unroll
            for (int mi = 0; mi < 2; mi++) {
                uint32_t ad = st + aLds0 + (uint32_t)(mi * 16 * ASTRIDE_B + s * 32);
                LDS64(a[mi][0], a[mi][2], ad);
                LDS64(a[mi][1], a[mi][3], ad + 8 * ASTRIDE_B);
            }
            uint32_t b[8][2];
#pragma unroll
            for (int nj = 0; nj < 8; nj++) {
                uint32_t bd = st + bLds0 + (uint32_t)(nj * 8 * ASTRIDE_B + s * 32);
                LDS64(b[nj][0], b[nj][1], bd);
            }
#pragma unroll
            for (int mi = 0; mi < 2; mi++)
#pragma unroll
                for (int nj = 0; nj < 8; nj++)
                    MMA_F16(acc[mi][nj], a[mi], b[nj]);
        }

        if ((c & 3) == 3) {                      // end of n-chunk: phases (no barriers)
            const int n0 = (c >> 2) * BN;
#pragma unroll
            for (int mi = 0; mi < 2; mi++)
#pragma unroll
                for (int qh = 0; qh < 2; qh++) {
                    const int r = wm * 32 + mi * 16 + g + 8 * qh;
                    float m = -3.4e38f;
#pragma unroll
                    for (int nj = 0; nj < 8; nj++) {
                        const int n = n0 + wn * 64 + nj * 8 + 2 * t;
                        acc[mi][nj][2 * qh]     -= ehs[n];
                        acc[mi][nj][2 * qh + 1] -= ehs[n + 1];
                        m = fmaxf(m, fmaxf(acc[mi][nj][2 * qh], acc[mi][nj][2 * qh + 1]));
                    }
                    m = fmaxf(m, __shfl_xor_sync(0xffffffffu, m, 1));
                    m = fmaxf(m, __shfl_xor_sync(0xffffffffu, m, 2));
                    if (t == 0) atomicMax(&sMax[r], fenc(m));
                }
#pragma unroll
            for (int mi = 0; mi < 2; mi++)
#pragma unroll
                for (int qh = 0; qh < 2; qh++) {
                    const int r = wm * 32 + mi * 16 + g + 8 * qh;
                    const float thr = fdec(sMax[r])
                                    - (0.002f * sqrtf(sXsq[r] * maxEsq) + 0.03f);
#pragma unroll
                    for (int nj = 0; nj < 8; nj++) {
                        const int n = n0 + wn * 64 + nj * 8 + 2 * t;
                        if (acc[mi][nj][2 * qh] >= thr) {
                            int p = atomicAdd(&sCnt[r], 1);
                            if (p < CAP) sList[r * CAP + p] = n;
                        }
                        if (acc[mi][nj][2 * qh + 1] >= thr) {
                            int p = atomicAdd(&sCnt[r], 1);
                            if (p < CAP) sList[r * CAP + p] = n + 1;
                        }
                    }
                }
#pragma unroll
            for (int mi = 0; mi < 2; mi++)
#pragma unroll
                for (int nj = 0; nj < 8; nj++)
#pragma unroll
                    for (int q = 0; q < 4; q++) acc[mi][nj][q] = 0.f;
        }
        __syncthreads();
    }

    if (tid < BM) g_cnt[row0 + tid] = sCnt[tid];
    for (int i = tid; i < BM * CAP; i += NT) g_list[row0 * CAP + i] = sList[i];
#undef ISSUE
}

// ---- double-float helpers (fp32 pipe; FP64 is fused-off on B300) ----
__device__ __forceinline__ void df_renorm(float& h, float& l) {
    float s = h + l;
    l = l - (s - h);
    h = s;
}
__device__ __forceinline__ void df_add(float& ah, float& al, float bh, float bl) {
    float s = ah + bh;
    float v = s - ah;
    float e = (ah - (s - v)) + (bh - v);
    float l = e + al + bl;
    ah = s; al = l;
    df_renorm(ah, al);
}

__global__ __launch_bounds__(256)
void rescue(const float* __restrict__ X, const float* __restrict__ E,
            float* __restrict__ out) {
    const int lane = threadIdx.x & 31;
    const int row  = blockIdx.x * 8 + (threadIdx.x >> 5);

    const float4* X4 = reinterpret_cast<const float4*>(X + (size_t)row * D);
    float4 x0 = X4[lane], x1 = X4[lane + 32];
    const float xv[8] = { x0.x, x0.y, x0.z, x0.w, x1.x, x1.y, x1.z, x1.w };

    const int cnt = g_cnt[row];
    const bool fallback = (cnt > CAP);
    const int total = fallback ? NCODES : cnt;

    float bh = -3.4e38f, bl = 0.f;
    int   besti = NCODES;
    for (int c = 0; c < total; c++) {
        const int idx = fallback ? c : g_list[row * CAP + c];
        const float4* E4r = reinterpret_cast<const float4*>(E + (size_t)idx * D);
        float4 e0 = E4r[lane], e1 = E4r[lane + 32];
        const float ev[8] = { e0.x, e0.y, e0.z, e0.w, e1.x, e1.y, e1.z, e1.w };

        float s = 0.f, comp = 0.f;
#pragma unroll
        for (int j = 0; j < 8; j++) {
            float p    = fmaf(-0.5f, ev[j], xv[j]);
            float prod = ev[j] * p;
            float perr = fmaf(ev[j], p, -prod);
            float tsum = s + prod;
            float v    = tsum - s;
            float serr = (s - (tsum - v)) + (prod - v);
            s = tsum;
            comp += serr + perr;
        }
        float h = s, l = comp;
        df_renorm(h, l);
#pragma unroll
        for (int off = 16; off > 0; off >>= 1) {
            float oh = __shfl_xor_sync(0xffffffffu, h, off);
            float ol = __shfl_xor_sync(0xffffffffu, l, off);
            df_add(h, l, oh, ol);
        }

        bool gt = (h > bh) || (h == bh && l > bl);
        bool eq = (h == bh) && (l == bl);
        if (gt || (eq && idx < besti)) { bh = h; bl = l; besti = idx; }
    }

    const float4* Eb = reinterpret_cast<const float4*>(E + (size_t)besti * D);
    float4* O4 = reinterpret_cast<float4*>(out + (size_t)row * D);
    O4[lane]      = Eb[lane];
    O4[lane + 32] = Eb[lane + 32];
}

extern "C" void kernel_launch(void* const* d_in, const int* in_sizes, int n_in,
                              void* d_out, int out_size) {
    const float* x = (const float*)d_in[0];     // [16,1024,256] f32
    const float* E = (const float*)d_in[1];     // [1024,256]    f32
    float* out = (float*)d_out;

    prep_e<<<NCODES * 16 / 256, 256>>>(E);
    prep_x<<<ROWS_TOTAL * 16 / 256, 256>>>(x);

    cudaFuncSetAttribute(vq_mma, cudaFuncAttributeMaxDynamicSharedMemorySize, SMEM_TOTAL);
    vq_mma<<<ROWS_TOTAL / BM, NT, SMEM_TOTAL>>>();

    rescue<<<ROWS_TOTAL / 8, 256>>>(x, E, out);
}

// round 13
// speedup vs baseline: 2.8528x; 1.0933x over previous
#include <cuda_runtime.h>
#include <cuda_fp16.h>
#include <cstdint>

#define D          256
#define NCODES     1024
#define ROWS_TOTAL 16384
#define BM         128
#define BN         256
#define NCHUNK     16        // 4 n-chunks x 4 k-chunks of 64
#define CAP        16
#define NT         512

#define ASTRIDE_B   160
#define ACHUNK_B    (BM * ASTRIDE_B)              // 20480 per k-chunk
#define A_FULL      0                             // 4 k-chunks resident: 81920
#define B_OFF       81920
#define B_STAGE     (BN * ASTRIDE_B)              // 40960
#define EHALF_OFF   (B_OFF + 3 * B_STAGE)         // 204800
#define XSQ_OFF     (EHALF_OFF + NCODES * 4)      // 208896
#define SMAX_OFF    (XSQ_OFF + BM * 4)            // 209408
#define SCNT_OFF    (SMAX_OFF + BM * 4)           // 209920
#define SIDX_OFF    (SCNT_OFF + BM * 4)           // 210432
#define SLIST_OFF   (SIDX_OFF + BM * 4)           // 210944
#define SMEM_TOTAL  (SLIST_OFF + BM * CAP * 8)    // 227328

__device__ __half g_Ec[(size_t)NCODES * D];        // 0.5 MB
__device__ float  g_e_half[NCODES];
__device__ int    g_maxEsq_bits;                   // atomicMax idempotent across replays

__device__ __forceinline__ constexpr int ilv16(int k) {
    return 4 * ((k & 7) >> 1) + 2 * (k >> 3) + (k & 1);
}
__device__ __forceinline__ unsigned fenc(float f) {
    unsigned u = __float_as_uint(f);
    return (u & 0x80000000u) ? ~u : (u | 0x80000000u);
}
__device__ __forceinline__ float fdec(unsigned u) {
    return __uint_as_float((u & 0x80000000u) ? (u ^ 0x80000000u) : ~u);
}

__global__ void prep_e(const float* __restrict__ E) {
    int gi = blockIdx.x * blockDim.x + threadIdx.x;
    const float4* src = reinterpret_cast<const float4*>(E) + (size_t)gi * 4;
    float4 v0 = src[0], v1 = src[1], v2 = src[2], v3 = src[3];
    float f[16] = { v0.x, v0.y, v0.z, v0.w, v1.x, v1.y, v1.z, v1.w,
                    v2.x, v2.y, v2.z, v2.w, v3.x, v3.y, v3.z, v3.w };
    __half h[16];
    float s = 0.f;
#pragma unroll
    for (int j = 0; j < 16; j++) { h[ilv16(j)] = __float2half_rn(f[j]); s += f[j] * f[j]; }
    uint4* dst = reinterpret_cast<uint4*>(g_Ec) + (size_t)gi * 2;
    dst[0] = reinterpret_cast<const uint4*>(h)[0];
    dst[1] = reinterpret_cast<const uint4*>(h)[1];
#pragma unroll
    for (int off = 8; off > 0; off >>= 1)
        s += __shfl_down_sync(0xffffffffu, s, off, 16);
    if ((gi & 15) == 0) {
        g_e_half[gi >> 4] = 0.5f * s;
        atomicMax(&g_maxEsq_bits, __float_as_int(s));
    }
}

static __device__ __forceinline__ uint32_t smem_u32(const void* p) {
    uint32_t a;
    asm("{ .reg .u64 t; cvta.to.shared.u64 t, %1; cvt.u32.u64 %0, t; }" : "=r"(a) : "l"(p));
    return a;
}
#define CP16(dst, src) asm volatile("cp.async.cg.shared.global [%0], [%1], 16;" :: "r"(dst), "l"(src) : "memory")
#define LDS64(r0, r1, a) asm volatile("ld.shared.v2.b32 {%0,%1}, [%2];" : "=r"(r0), "=r"(r1) : "r"(a))
#define MMA_F16(c, a, b) \
    asm volatile("mma.sync.aligned.m16n8k16.row.col.f32.f16.f16.f32 " \
                 "{%0,%1,%2,%3}, {%4,%5,%6,%7}, {%8,%9}, {%0,%1,%2,%3};" \
                 : "+f"((c)[0]), "+f"((c)[1]), "+f"((c)[2]), "+f"((c)[3]) \
                 : "r"((a)[0]), "r"((a)[1]), "r"((a)[2]), "r"((a)[3]), "r"((b)[0]), "r"((b)[1]))

// double-float helpers (fp32 pipe; FP64 is fused-off on B300)
__device__ __forceinline__ void df_renorm(float& h, float& l) {
    float s = h + l; l = l - (s - h); h = s;
}
__device__ __forceinline__ void df_add(float& ah, float& al, float bh, float bl) {
    float s = ah + bh;
    float v = s - ah;
    float e = (ah - (s - v)) + (bh - v);
    float l = e + al + bl;
    ah = s; al = l;
    df_renorm(ah, al);
}
// warp-collective compensated score of code idx vs xv[8] (per-lane slice)
__device__ __forceinline__ void cscore(const float* __restrict__ E, int idx, int lane,
                                       const float xv[8], float& h, float& l) {
    const float4* E4r = reinterpret_cast<const float4*>(E + (size_t)idx * D);
    float4 e0 = E4r[lane], e1 = E4r[lane + 32];
    const float ev[8] = { e0.x, e0.y, e0.z, e0.w, e1.x, e1.y, e1.z, e1.w };
    float s = 0.f, comp = 0.f;
#pragma unroll
    for (int j = 0; j < 8; j++) {
        float p    = fmaf(-0.5f, ev[j], xv[j]);
        float prod = ev[j] * p;
        float perr = fmaf(ev[j], p, -prod);
        float tsum = s + prod;
        float v    = tsum - s;
        float serr = (s - (tsum - v)) + (prod - v);
        s = tsum; comp += serr + perr;
    }
    h = s; l = comp;
    df_renorm(h, l);
#pragma unroll
    for (int off = 16; off > 0; off >>= 1) {
        float oh = __shfl_xor_sync(0xffffffffu, h, off);
        float ol = __shfl_xor_sync(0xffffffffu, l, off);
        df_add(h, l, oh, ol);
    }
}

__global__ __launch_bounds__(NT, 1)
void vq_mma(const float* __restrict__ X, const float* __restrict__ E,
            float* __restrict__ out) {
    extern __shared__ char smem[];
    const uint32_t sb = smem_u32(smem);
    float*    ehs   = (float*)(smem + EHALF_OFF);
    float*    sXsq  = (float*)(smem + XSQ_OFF);
    unsigned* sMax  = (unsigned*)(smem + SMAX_OFF);
    int*      sCnt  = (int*)(smem + SCNT_OFF);
    int*      sIdx  = (int*)(smem + SIDX_OFF);
    int2*     sList = (int2*)(smem + SLIST_OFF);

    const int tid  = threadIdx.x;
    const int lane = tid & 31, wid = tid >> 5;
    const int wm = wid & 3, wn = wid >> 2;              // 4(M) x 4(N)
    const int g = lane >> 2, t = lane & 3;
    const int row0 = blockIdx.x * BM;
    const float maxEsq = __int_as_float(g_maxEsq_bits);

    // B cp.async unit assignment: 4 units/thread
    const int urow = tid >> 3, uj = tid & 7;            // urow 0..63
    const char* bSrcB = (const char*)(g_Ec + (size_t)urow * D) + uj * 16;
    const uint32_t bDst0 = sb + B_OFF + urow * ASTRIDE_B + uj * 16;
    const uint32_t aLds0 = sb + (uint32_t)(A_FULL + (wm * 32 + g) * ASTRIDE_B + t * 8);
    const uint32_t bLds0 = sb + (uint32_t)(B_OFF + (wn * 64 + g) * ASTRIDE_B + t * 8);

#define ISSUE_B(c) do {                                                          \
        const uint32_t _st = (uint32_t)((c) % 3) * B_STAGE;                      \
        const int _boff = ((c) >> 2) * 131072 + ((c) & 3) * 128;                 \
        _Pragma("unroll")                                                        \
        for (int i = 0; i < 4; i++) CP16(_st + bDst0 + i * (64 * ASTRIDE_B),     \
                                         bSrcB + _boff + i * 32768);             \
        asm volatile("cp.async.commit_group;" ::: "memory");                     \
    } while (0)

    ISSUE_B(0);
    ISSUE_B(1);

    // ---- fused prep_x: X -> fp16 interleaved resident A-tile + xsq ----
    {
        const int crow = tid >> 2, cq = tid & 3;
        const float4* xs = reinterpret_cast<const float4*>(X + (size_t)(row0 + crow) * D);
        float s = 0.f;
#pragma unroll
        for (int g4 = 0; g4 < 4; g4++) {
            const int gi = cq + g4 * 4;                 // one group per k-chunk
            float4 v0 = xs[gi * 4], v1 = xs[gi * 4 + 1], v2 = xs[gi * 4 + 2], v3 = xs[gi * 4 + 3];
            float f[16] = { v0.x, v0.y, v0.z, v0.w, v1.x, v1.y, v1.z, v1.w,
                            v2.x, v2.y, v2.z, v2.w, v3.x, v3.y, v3.z, v3.w };
            __half h[16];
#pragma unroll
            for (int j = 0; j < 16; j++) { h[ilv16(j)] = __float2half_rn(f[j]); s += f[j] * f[j]; }
            uint4* dst = reinterpret_cast<uint4*>(smem + A_FULL + g4 * ACHUNK_B
                                                  + crow * ASTRIDE_B + cq * 32);
            dst[0] = reinterpret_cast<const uint4*>(h)[0];
            dst[1] = reinterpret_cast<const uint4*>(h)[1];
        }
        s += __shfl_xor_sync(0xffffffffu, s, 1);
        s += __shfl_xor_sync(0xffffffffu, s, 2);
        if (cq == 0) sXsq[crow] = s;
    }

    for (int i = tid; i < NCODES; i += NT) ehs[i] = g_e_half[i];
    if (tid < BM) { sMax[tid] = 0u; sCnt[tid] = 0; }

    float acc[2][8][4];
#pragma unroll
    for (int mi = 0; mi < 2; mi++)
#pragma unroll
        for (int nj = 0; nj < 8; nj++)
#pragma unroll
            for (int q = 0; q < 4; q++) acc[mi][nj][q] = 0.f;

#pragma unroll 1
    for (int c = 0; c < NCHUNK; c++) {
        if (c < NCHUNK - 1) asm volatile("cp.async.wait_group 1;" ::: "memory");
        else                asm volatile("cp.async.wait_group 0;" ::: "memory");
        __syncthreads();     // stage c visible to all; prior-stage consumers done

        const uint32_t stB = (uint32_t)(c % 3) * B_STAGE;
        const uint32_t stA = (uint32_t)(c & 3) * ACHUNK_B;
#pragma unroll
        for (int s = 0; s < 4; s++) {
            uint32_t a[2][4];
#pragma unroll
            for (int mi = 0; mi < 2; mi++) {
                uint32_t ad = stA + aLds0 + (uint32_t)(mi * 16 * ASTRIDE_B + s * 32);
                LDS64(a[mi][0], a[mi][2], ad);
                LDS64(a[mi][1], a[mi][3], ad + 8 * ASTRIDE_B);
            }
            uint32_t b[8][2];
#pragma unroll
            for (int nj = 0; nj < 8; nj++) {
                uint32_t bd = stB + bLds0 + (uint32_t)(nj * 8 * ASTRIDE_B + s * 32);
                LDS64(b[nj][0], b[nj][1], bd);
            }
#pragma unroll
            for (int mi = 0; mi < 2; mi++)
#pragma unroll
                for (int nj = 0; nj < 8; nj++)
                    MMA_F16(acc[mi][nj], a[mi], b[nj]);
        }

        if ((c & 3) == 3) {                      // end of n-chunk: phases (no barriers)
            const int n0 = (c >> 2) * BN;
#pragma unroll
            for (int mi = 0; mi < 2; mi++)
#pragma unroll
                for (int qh = 0; qh < 2; qh++) {
                    const int r = wm * 32 + mi * 16 + g + 8 * qh;
                    float m = -3.4e38f;
#pragma unroll
                    for (int nj = 0; nj < 8; nj++) {
                        const int n = n0 + wn * 64 + nj * 8 + 2 * t;
                        acc[mi][nj][2 * qh]     -= ehs[n];
                        acc[mi][nj][2 * qh + 1] -= ehs[n + 1];
                        m = fmaxf(m, fmaxf(acc[mi][nj][2 * qh], acc[mi][nj][2 * qh + 1]));
                    }
                    m = fmaxf(m, __shfl_xor_sync(0xffffffffu, m, 1));
                    m = fmaxf(m, __shfl_xor_sync(0xffffffffu, m, 2));
                    if (t == 0) atomicMax(&sMax[r], fenc(m));
                }
#pragma unroll
            for (int mi = 0; mi < 2; mi++)
#pragma unroll
                for (int qh = 0; qh < 2; qh++) {
                    const int r = wm * 32 + mi * 16 + g + 8 * qh;
                    const float thr = fdec(sMax[r])
                                    - (0.002f * sqrtf(sXsq[r] * maxEsq) + 0.03f);
#pragma unroll
                    for (int nj = 0; nj < 8; nj++) {
                        const int n = n0 + wn * 64 + nj * 8 + 2 * t;
#pragma unroll
                        for (int q = 0; q < 2; q++) {
                            float sc = acc[mi][nj][2 * qh + q];
                            if (sc >= thr) {
                                int p = atomicAdd(&sCnt[r], 1);
                                if (p < CAP)
                                    sList[r * CAP + p] = make_int2(__float_as_int(sc), n + q);
                            }
                        }
                    }
                }
#pragma unroll
            for (int mi = 0; mi < 2; mi++)
#pragma unroll
                for (int nj = 0; nj < 8; nj++)
#pragma unroll
                    for (int q = 0; q < 4; q++) acc[mi][nj][q] = 0.f;
        }
        if (c + 2 < NCHUNK) ISSUE_B(c + 2);
    }
    __syncthreads();                              // lists complete

    // ---- fused rescue: one warp per 8 rows ----
    for (int r = wid * 8; r < wid * 8 + 8; r++) {
        const int cnt = sCnt[r];
        int best = 0;
        if (cnt <= CAP) {
            float sc = -3.4e38f; int id = 0;
            if (lane < cnt) { int2 e = sList[r * CAP + lane]; sc = __int_as_float(e.x); id = e.y; }
            float msc = sc;
#pragma unroll
            for (int off = 16; off > 0; off >>= 1)
                msc = fmaxf(msc, __shfl_xor_sync(0xffffffffu, msc, off));
            const float thr = msc - (0.002f * sqrtf(sXsq[r] * maxEsq) + 0.03f);
            unsigned surv = __ballot_sync(0xffffffffu, lane < cnt && sc >= thr);
            if (__popc(surv) == 1) {
                best = __shfl_sync(0xffffffffu, id, __ffs(surv) - 1);
            } else {
                const float4* X4 = reinterpret_cast<const float4*>(X + (size_t)(row0 + r) * D);
                float4 x0 = X4[lane], x1 = X4[lane + 32];
                const float xv[8] = { x0.x, x0.y, x0.z, x0.w, x1.x, x1.y, x1.z, x1.w };
                float bh = -3.4e38f, bl = 0.f;
                int besti = NCODES;
                while (surv) {
                    int b = __ffs(surv) - 1; surv &= surv - 1;
                    int idx = __shfl_sync(0xffffffffu, id, b);
                    float h, l;
                    cscore(E, idx, lane, xv, h, l);
                    bool gt = (h > bh) || (h == bh && l > bl);
                    bool eq = (h == bh) && (l == bl);
                    if (gt || (eq && idx < besti)) { bh = h; bl = l; besti = idx; }
                }
                best = besti;
            }
        } else {                                  // overflow: exact full scan (rare)
            const float4* X4 = reinterpret_cast<const float4*>(X + (size_t)(row0 + r) * D);
            float4 x0 = X4[lane], x1 = X4[lane + 32];
            const float xv[8] = { x0.x, x0.y, x0.z, x0.w, x1.x, x1.y, x1.z, x1.w };
            float bh = -3.4e38f, bl = 0.f;
            int besti = NCODES;
            for (int idx = 0; idx < NCODES; idx++) {
                float h, l;
                cscore(E, idx, lane, xv, h, l);
                bool gt = (h > bh) || (h == bh && l > bl);
                bool eq = (h == bh) && (l == bl);
                if (gt || (eq && idx < besti)) { bh = h; bl = l; besti = idx; }
            }
            best = besti;
        }
        if (lane == 0) sIdx[r] = best;
    }
    __syncthreads();

    // ---- gather: out[row] = E[best] (coalesced float4) ----
    const float4* E4 = reinterpret_cast<const float4*>(E);
    float4*       O4 = reinterpret_cast<float4*>(out);
    const int col = tid & 63;
#pragma unroll
    for (int r = tid >> 6; r < BM; r += 8) {
        int idx = sIdx[r];
        O4[(size_t)(row0 + r) * (D / 4) + col] = E4[(size_t)idx * (D / 4) + col];
    }
#undef ISSUE_B
}

extern "C" void kernel_launch(void* const* d_in, const int* in_sizes, int n_in,
                              void* d_out, int out_size) {
    const float* x = (const float*)d_in[0];     // [16,1024,256] f32
    const float* E = (const float*)d_in[1];     // [1024,256]    f32
    float* out = (float*)d_out;

    prep_e<<<NCODES * 16 / 256, 256>>>(E);

    cudaFuncSetAttribute(vq_mma, cudaFuncAttributeMaxDynamicSharedMemorySize, SMEM_TOTAL);
    vq_mma<<<ROWS_TOTAL / BM, NT, SMEM_TOTAL>>>(x, E, out);
}